// round 15
// baseline (speedup 1.0000x reference)
#include <cuda_runtime.h>
#include <cuda_bf16.h>
#include <cstdint>

// Problem constants
#define NB 4
#define NN 1024
#define MM 1024
#define CC 768
#define HH 12
#define DD 64
#define ROWS (NB * NN)        // 4096
#define ATT_SCALE 0.125f      // 64^-0.5 (exact power of two)

// ---------------------------------------------------------------------------
// Scratch (static device arrays — allocation-free per harness rules)
// ---------------------------------------------------------------------------
__device__ __nv_bfloat16 g_xh[ROWS * CC], g_xl[ROWS * CC];
__device__ __nv_bfloat16 g_yh[ROWS * CC], g_yl[ROWS * CC];
__device__ __nv_bfloat16 g_qh[ROWS * CC], g_ql[ROWS * CC];   // pre-scaled by 0.125
__device__ __nv_bfloat16 g_kh[ROWS * CC], g_kl[ROWS * CC];
__device__ __nv_bfloat16 g_vh[ROWS * CC], g_vl[ROWS * CC];
__device__ __nv_bfloat16 g_oh[ROWS * CC], g_ol[ROWS * CC];
__device__ __nv_bfloat16 g_wqh[CC * CC], g_wql[CC * CC];
__device__ __nv_bfloat16 g_wkh[CC * CC], g_wkl[CC * CC];
__device__ __nv_bfloat16 g_wvh[CC * CC], g_wvl[CC * CC];
__device__ __nv_bfloat16 g_wph[CC * CC], g_wpl[CC * CC];

// Split-KV attention partials (fp32, unnormalized) + per-row softmax state
__device__ float g_p0[ROWS * CC], g_p1[ROWS * CC];
__device__ float g_m0a[HH * ROWS], g_l0a[HH * ROWS];
__device__ float g_m1a[HH * ROWS], g_l1a[HH * ROWS];

// Dynamic tile counters (reset by cvt_all each launch/replay)
__device__ int g_ctrP;
__device__ int g_ctrO;

// ---------------------------------------------------------------------------
// Helpers
// ---------------------------------------------------------------------------
__device__ __forceinline__ uint32_t smem_u32(const void* p) {
    uint32_t a;
    asm("{ .reg .u64 t; cvta.to.shared.u64 t, %1; cvt.u32.u64 %0, t; }"
        : "=r"(a) : "l"(p));
    return a;
}

__device__ __forceinline__ void mma16816(float d[4],
    uint32_t a0, uint32_t a1, uint32_t a2, uint32_t a3,
    uint32_t b0, uint32_t b1)
{
    asm volatile(
        "mma.sync.aligned.m16n8k16.row.col.f32.bf16.bf16.f32 "
        "{%0,%1,%2,%3}, {%4,%5,%6,%7}, {%8,%9}, {%0,%1,%2,%3};"
        : "+f"(d[0]), "+f"(d[1]), "+f"(d[2]), "+f"(d[3])
        : "r"(a0), "r"(a1), "r"(a2), "r"(a3), "r"(b0), "r"(b1));
}

__device__ __forceinline__ void ldsm4(uint32_t r[4], uint32_t addr) {
    asm volatile("ldmatrix.sync.aligned.m8n8.x4.shared.b16 {%0,%1,%2,%3}, [%4];"
                 : "=r"(r[0]), "=r"(r[1]), "=r"(r[2]), "=r"(r[3]) : "r"(addr));
}
__device__ __forceinline__ void ldsm4t(uint32_t r[4], uint32_t addr) {
    asm volatile("ldmatrix.sync.aligned.m8n8.x4.trans.shared.b16 {%0,%1,%2,%3}, [%4];"
                 : "=r"(r[0]), "=r"(r[1]), "=r"(r[2]), "=r"(r[3]) : "r"(addr));
}

__device__ __forceinline__ void cp16(uint32_t smem_dst, const void* gsrc) {
    asm volatile("cp.async.cg.shared.global [%0], [%1], 16;"
                 :: "r"(smem_dst), "l"(gsrc));
}
#define CP_COMMIT() asm volatile("cp.async.commit_group;" ::: "memory")
#define CP_WAIT0()  asm volatile("cp.async.wait_group 0;" ::: "memory")
#define CP_WAIT1()  asm volatile("cp.async.wait_group 1;" ::: "memory")

// Split two fp32 into packed bf16-hi (truncation) + bf16-lo (rounded residual)
__device__ __forceinline__ void pack_split(float v0, float v1,
                                           uint32_t& hp, uint32_t& lp)
{
    const uint32_t u0 = __float_as_uint(v0), u1 = __float_as_uint(v1);
    hp = __byte_perm(u0, u1, 0x7632);
    const float r0 = v0 - __uint_as_float(u0 & 0xFFFF0000u);
    const float r1 = v1 - __uint_as_float(u1 & 0xFFFF0000u);
    __nv_bfloat162 t = __floats2bfloat162_rn(r0, r1);
    lp = *reinterpret_cast<uint32_t*>(&t);
}

__device__ __forceinline__ void split_store(__nv_bfloat16* H, __nv_bfloat16* L,
                                            size_t off, float v0, float v1)
{
    uint32_t hp, lp;
    pack_split(v0, v1, hp, lp);
    *reinterpret_cast<uint32_t*>(H + off) = hp;
    *reinterpret_cast<uint32_t*>(L + off) = lp;
}

// ---------------------------------------------------------------------------
// Fused fp32 -> bf16 hi/lo split for all six source arrays (+ counter reset)
// ---------------------------------------------------------------------------
#define A4 (ROWS * CC / 4)     // 786432 quads per activation
#define W4 (CC * CC / 4)       // 147456 quads per weight
#define CVT_TOTAL (2 * A4 + 4 * W4)

__global__ __launch_bounds__(256) void cvt_all(
    const float4* __restrict__ x, const float4* __restrict__ y,
    const float4* __restrict__ wq, const float4* __restrict__ wk,
    const float4* __restrict__ wv, const float4* __restrict__ wp)
{
    if (blockIdx.x == 0 && threadIdx.x == 0) { g_ctrP = 0; g_ctrO = 0; }

    int i = blockIdx.x * blockDim.x + threadIdx.x;
    const int stride = gridDim.x * blockDim.x;
    for (; i < CVT_TOTAL; i += stride) {
        const float4* s;
        uint2 *h, *l;
        int j;
        if (i < A4)            { s = x; h = (uint2*)g_xh; l = (uint2*)g_xl; j = i; }
        else if (i < 2 * A4)   { s = y; h = (uint2*)g_yh; l = (uint2*)g_yl; j = i - A4; }
        else {
            const int t = i - 2 * A4;
            const int w = t / W4;
            j = t - w * W4;
            if (w == 0)      { s = wq; h = (uint2*)g_wqh; l = (uint2*)g_wql; }
            else if (w == 1) { s = wk; h = (uint2*)g_wkh; l = (uint2*)g_wkl; }
            else if (w == 2) { s = wv; h = (uint2*)g_wvh; l = (uint2*)g_wvl; }
            else             { s = wp; h = (uint2*)g_wph; l = (uint2*)g_wpl; }
        }
        const float4 v = s[j];
        uint32_t h0, l0, h1, l1;
        pack_split(v.x, v.y, h0, l0);
        pack_split(v.z, v.w, h1, l1);
        h[j] = make_uint2(h0, h1);
        l[j] = make_uint2(l0, l1);
    }
}

// ---------------------------------------------------------------------------
// Persistent mma.sync NT GEMM (R13 winner config, frozen):
// bf16 hi/lo, tile 128x64, BK=64, 2-stage cp.async double buffer,
// 256 threads (8 warps, 2m x 4n), warp tile 64x16, 2 CTAs/SM, tile stealing.
// ---------------------------------------------------------------------------
#define GST 72                         // padded row stride (elems), 144B
#define GTA (128 * GST)                // A tile elems (hi or lo)
#define GTB (64 * GST)                 // B tile elems (hi or lo)
#define GSTG (2 * GTA + 2 * GTB)       // elems per stage = 27648
#define GEMM_SMEM (2 * GSTG * 2)       // 110592 bytes
#define KSTEPS (CC / 64)               // 12
#define TILES_PER_MAT (32 * 12)        // 384
#define NT_PROJ (3 * TILES_PER_MAT)    // 1152
#define NT_OPROJ TILES_PER_MAT         // 384
#define GEMM_GRID 296                  // 2 per SM x 148

template <bool OPROJ>
__global__ __launch_bounds__(256, 2) void gemm_all(
    const float* __restrict__ rowbias,   // yw (proj) / nullptr
    const float* __restrict__ colbias,   // nullptr / bp
    float* __restrict__ outF)            // nullptr / out
{
    extern __shared__ char sm[];
    const uint32_t sbase = smem_u32(sm);
    __shared__ int s_tile;

    const int tid = threadIdx.x;
    const int wid = tid >> 5, lane = tid & 31;
    const int wm = wid >> 2, wn = wid & 3;          // 2 x 4 warp grid
    const int lrow = lane & 15, lcol = (lane >> 4) * 8;
    const int NT = OPROJ ? NT_OPROJ : NT_PROJ;

    for (;;) {
        if (tid == 0)
            s_tile = atomicAdd(OPROJ ? &g_ctrO : &g_ctrP, 1);
        __syncthreads();
        const int t = s_tile;
        if (t >= NT) break;

        const int z = OPROJ ? 3 : (t / TILES_PER_MAT);
        const int rem = OPROJ ? t : (t - z * TILES_PER_MAT);
        const int row0 = (rem & 31) * 128;
        const int col0 = (rem >> 5) * 64;

        const __nv_bfloat16 *Ah, *Al, *Bh, *Bl;
        __nv_bfloat16 *OH = nullptr, *OL = nullptr;
        if (OPROJ) {
            Ah = g_oh; Al = g_ol; Bh = g_wph; Bl = g_wpl;
        } else if (z == 0) {
            Ah = g_xh; Al = g_xl; Bh = g_wqh; Bl = g_wql; OH = g_qh; OL = g_ql;
        } else if (z == 1) {
            Ah = g_yh; Al = g_yl; Bh = g_wkh; Bl = g_wkl; OH = g_kh; OL = g_kl;
        } else {
            Ah = g_yh; Al = g_yl; Bh = g_wvh; Bl = g_wvl; OH = g_vh; OL = g_vl;
        }

        float acc[4][2][4];
        #pragma unroll
        for (int i = 0; i < 4; i++)
            #pragma unroll
            for (int j = 0; j < 2; j++)
                #pragma unroll
                for (int e = 0; e < 4; e++) acc[i][j][e] = 0.0f;

        auto stage_load = [&](int st, int stage) {
            const int k0 = st * 64;
            #pragma unroll
            for (int j = 0; j < 12; j++) {
                const int ch = tid + j * 256;
                const __nv_bfloat16* src;
                uint32_t soff;
                int r, c;
                if (ch < 1024) {
                    r = ch >> 3; c = ch & 7;
                    src = Ah + (size_t)(row0 + r) * CC;
                    soff = (uint32_t)(r * GST + c * 8);
                } else if (ch < 2048) {
                    const int q = ch - 1024; r = q >> 3; c = q & 7;
                    src = Al + (size_t)(row0 + r) * CC;
                    soff = (uint32_t)(GTA + r * GST + c * 8);
                } else if (ch < 2560) {
                    const int q = ch - 2048; r = q >> 3; c = q & 7;
                    src = Bh + (size_t)(col0 + r) * CC;
                    soff = (uint32_t)(2 * GTA + r * GST + c * 8);
                } else {
                    const int q = ch - 2560; r = q >> 3; c = q & 7;
                    src = Bl + (size_t)(col0 + r) * CC;
                    soff = (uint32_t)(2 * GTA + GTB + r * GST + c * 8);
                }
                cp16(sbase + (uint32_t)(stage * GSTG) * 2 + soff * 2,
                     src + k0 + c * 8);
            }
            CP_COMMIT();
        };

        stage_load(0, 0);

        for (int st = 0; st < KSTEPS; st++) {
            const int buf = st & 1;
            if (st + 1 < KSTEPS) {
                stage_load(st + 1, buf ^ 1);
                CP_WAIT1();
            } else {
                CP_WAIT0();
            }
            __syncthreads();

            const uint32_t Ab = sbase + (uint32_t)(buf * GSTG) * 2 +
                                (uint32_t)((wm * 64 + lrow) * GST + lcol) * 2;
            const uint32_t Bb = sbase + (uint32_t)(buf * GSTG + 2 * GTA) * 2 +
                                (uint32_t)((wn * 16 + lrow) * GST + lcol) * 2;

            #pragma unroll
            for (int kk = 0; kk < 4; kk++) {
                uint32_t afh[4][4], afl[4][4];
                #pragma unroll
                for (int mt = 0; mt < 4; mt++) {
                    const uint32_t o2 = (uint32_t)(mt * 16 * GST + kk * 16) * 2;
                    ldsm4(afh[mt], Ab + o2);
                    ldsm4(afl[mt], Ab + (uint32_t)GTA * 2 + o2);
                }
                uint32_t bh[4], bl[4];
                const uint32_t o2 = (uint32_t)(kk * 16) * 2;
                ldsm4(bh, Bb + o2);
                ldsm4(bl, Bb + (uint32_t)GTB * 2 + o2);
                #pragma unroll
                for (int mt = 0; mt < 4; mt++) {
                    mma16816(acc[mt][0], afh[mt][0], afh[mt][1], afh[mt][2], afh[mt][3], bh[0], bh[2]);
                    mma16816(acc[mt][0], afh[mt][0], afh[mt][1], afh[mt][2], afh[mt][3], bl[0], bl[2]);
                    mma16816(acc[mt][0], afl[mt][0], afl[mt][1], afl[mt][2], afl[mt][3], bh[0], bh[2]);
                    mma16816(acc[mt][1], afh[mt][0], afh[mt][1], afh[mt][2], afh[mt][3], bh[1], bh[3]);
                    mma16816(acc[mt][1], afh[mt][0], afh[mt][1], afh[mt][2], afh[mt][3], bl[1], bl[3]);
                    mma16816(acc[mt][1], afl[mt][0], afl[mt][1], afl[mt][2], afl[mt][3], bh[1], bh[3]);
                }
            }
            __syncthreads();
        }

        // Epilogue
        const float scale = (!OPROJ && z == 0) ? ATT_SCALE : 1.0f;
        #pragma unroll
        for (int mt = 0; mt < 4; mt++) {
            const int r_lo = row0 + wm * 64 + mt * 16 + (lane >> 2);
            const int r_hi = r_lo + 8;
            const float rb_lo = (!OPROJ && z == 1) ? rowbias[r_lo] : 0.0f;
            const float rb_hi = (!OPROJ && z == 1) ? rowbias[r_hi] : 0.0f;
            #pragma unroll
            for (int nt = 0; nt < 2; nt++) {
                const int c = col0 + wn * 16 + nt * 8 + 2 * (lane & 3);
                const float cb0 = OPROJ ? colbias[c] : 0.0f;
                const float cb1 = OPROJ ? colbias[c + 1] : 0.0f;
                const float v0 = acc[mt][nt][0] * scale + rb_lo + cb0;
                const float v1 = acc[mt][nt][1] * scale + rb_lo + cb1;
                const float v2 = acc[mt][nt][2] * scale + rb_hi + cb0;
                const float v3 = acc[mt][nt][3] * scale + rb_hi + cb1;
                if (OPROJ) {
                    *(float2*)(outF + (size_t)r_lo * CC + c) = make_float2(v0, v1);
                    *(float2*)(outF + (size_t)r_hi * CC + c) = make_float2(v2, v3);
                } else {
                    split_store(OH, OL, (size_t)r_lo * CC + c, v0, v1);
                    split_store(OH, OL, (size_t)r_hi * CC + c, v2, v3);
                }
            }
        }
        __syncthreads();
    }
}

// ---------------------------------------------------------------------------
// Split-KV flash attention (mma.sync, bf16 hi/lo), cp.async double-buffered.
// grid (NN/128, NB*HH, 2): z selects key half (512 keys = 8 blocks of 64).
// Writes UNNORMALIZED fp32 O partial + per-row (m, l) to scratch.
// Q pre-scaled by ATT_SCALE at projection time.
// ---------------------------------------------------------------------------
#define AST 72
#define KVT (64 * AST)                 // 4608 elems
#define KVSTG (4 * KVT)                // 18432 elems (also exactly Q hi+lo)
#define ATT_SMEM2 (2 * KVSTG * 2)      // 73728 bytes
#define NKVH 8                         // KV blocks per half

__global__ __launch_bounds__(256, 2) void attn_ms()
{
    extern __shared__ char sm[];
    const uint32_t sbase = smem_u32(sm);

    const int tid = threadIdx.x;
    const int wid = tid >> 5, lane = tid & 31;
    const int lrow = lane & 15, lcol = (lane >> 4) * 8;
    const int n0 = blockIdx.x * 128;
    const int b = blockIdx.y / HH, h = blockIdx.y % HH;
    const int zh = blockIdx.z;                 // key half
    const int kvofs = zh * 512;
    const size_t qrow0 = (size_t)(b * NN + n0);
    const size_t kvrow0 = (size_t)(b * MM);

    float* pO = zh ? g_p1 : g_p0;
    float* pM = zh ? g_m1a : g_m0a;
    float* pL = zh ? g_l1a : g_l0a;

    const int qa = tid >> 7;
    const __nv_bfloat16* qsrc = qa ? g_ql : g_qh;
    const int ka = tid >> 6;
    const __nv_bfloat16* ksrc = (ka == 0) ? g_kh : (ka == 1) ? g_kl
                              : (ka == 2) ? g_vh : g_vl;

    auto kv_load = [&](int m0i, int stage) {
        #pragma unroll
        for (int j = 0; j < 8; j++) {
            const int ch = (tid & 63) + j * 64;
            const int r = ch >> 3, c = ch & 7;
            cp16(sbase + (uint32_t)(stage * KVSTG + ka * KVT + r * AST + c * 8) * 2,
                 ksrc + (kvrow0 + m0i + r) * CC + h * DD + c * 8);
        }
        CP_COMMIT();
    };

    // ---- Q through stage 0: load, extract frags, release ----
    #pragma unroll
    for (int j = 0; j < 8; j++) {
        const int ch = (tid & 127) + j * 128;
        const int r = ch >> 3, c = ch & 7;
        cp16(sbase + (uint32_t)(qa * 128 * AST + r * AST + c * 8) * 2,
             qsrc + (qrow0 + r) * CC + h * DD + c * 8);
    }
    CP_COMMIT();
    CP_WAIT0();
    __syncthreads();

    uint32_t qfh[4][4], qfl[4][4];
    {
        const uint32_t qb = sbase + (uint32_t)((wid * 16 + lrow) * AST + lcol) * 2;
        #pragma unroll
        for (int kk = 0; kk < 4; kk++) {
            ldsm4(qfh[kk], qb + kk * 32);
            ldsm4(qfl[kk], qb + (uint32_t)(128 * AST) * 2 + kk * 32);
        }
    }
    __syncthreads();    // all warps done reading Q before stage 0 is reused

    kv_load(kvofs, 0);

    float m0 = -1e30f, m1 = -1e30f, l0 = 0.0f, l1 = 0.0f;
    float o[8][4];
    #pragma unroll
    for (int dt = 0; dt < 8; dt++)
        #pragma unroll
        for (int e = 0; e < 4; e++) o[dt][e] = 0.0f;

    for (int st = 0; st < NKVH; st++) {
        const int buf = st & 1;
        if (st + 1 < NKVH) {
            kv_load(kvofs + (st + 1) * 64, buf ^ 1);
            CP_WAIT1();
        } else {
            CP_WAIT0();
        }
        __syncthreads();

        const uint32_t kvb = sbase + (uint32_t)(buf * KVSTG) * 2;
        const uint32_t kA = kvb + (uint32_t)(lrow * AST + lcol) * 2;
        const uint32_t vA = kvb + (uint32_t)(2 * KVT + lrow * AST + lcol) * 2;
        const uint32_t LOFS = (uint32_t)KVT * 2;

        // ---- S = Q K^T (hi/lo 3-term), Q pre-scaled ----
        float s[8][4];
        #pragma unroll
        for (int nt = 0; nt < 8; nt++)
            #pragma unroll
            for (int e = 0; e < 4; e++) s[nt][e] = 0.0f;

        #pragma unroll
        for (int kg = 0; kg < 4; kg++) {
            #pragma unroll
            for (int kk = 0; kk < 4; kk++) {
                uint32_t bh[4], bl[4];
                const uint32_t o2 = (uint32_t)(kg * 16 * AST + kk * 16) * 2;
                ldsm4(bh, kA + o2);
                ldsm4(bl, kA + LOFS + o2);
                mma16816(s[2 * kg], qfh[kk][0], qfh[kk][1], qfh[kk][2], qfh[kk][3], bh[0], bh[2]);
                mma16816(s[2 * kg], qfh[kk][0], qfh[kk][1], qfh[kk][2], qfh[kk][3], bl[0], bl[2]);
                mma16816(s[2 * kg], qfl[kk][0], qfl[kk][1], qfl[kk][2], qfl[kk][3], bh[0], bh[2]);
                mma16816(s[2 * kg + 1], qfh[kk][0], qfh[kk][1], qfh[kk][2], qfh[kk][3], bh[1], bh[3]);
                mma16816(s[2 * kg + 1], qfh[kk][0], qfh[kk][1], qfh[kk][2], qfh[kk][3], bl[1], bl[3]);
                mma16816(s[2 * kg + 1], qfl[kk][0], qfl[kk][1], qfl[kk][2], qfl[kk][3], bh[1], bh[3]);
            }
        }

        // ---- online softmax ----
        float mx0 = -1e30f, mx1 = -1e30f;
        #pragma unroll
        for (int nt = 0; nt < 8; nt++) {
            mx0 = fmaxf(mx0, fmaxf(s[nt][0], s[nt][1]));
            mx1 = fmaxf(mx1, fmaxf(s[nt][2], s[nt][3]));
        }
        mx0 = fmaxf(mx0, __shfl_xor_sync(0xFFFFFFFFu, mx0, 1));
        mx0 = fmaxf(mx0, __shfl_xor_sync(0xFFFFFFFFu, mx0, 2));
        mx1 = fmaxf(mx1, __shfl_xor_sync(0xFFFFFFFFu, mx1, 1));
        mx1 = fmaxf(mx1, __shfl_xor_sync(0xFFFFFFFFu, mx1, 2));

        const float mn0 = fmaxf(m0, mx0), mn1 = fmaxf(m1, mx1);
        const float a0 = __expf(m0 - mn0), a1 = __expf(m1 - mn1);
        m0 = mn0; m1 = mn1;

        float sum0 = 0.0f, sum1 = 0.0f;
        #pragma unroll
        for (int nt = 0; nt < 8; nt++) {
            s[nt][0] = __expf(s[nt][0] - mn0); sum0 += s[nt][0];
            s[nt][1] = __expf(s[nt][1] - mn0); sum0 += s[nt][1];
            s[nt][2] = __expf(s[nt][2] - mn1); sum1 += s[nt][2];
            s[nt][3] = __expf(s[nt][3] - mn1); sum1 += s[nt][3];
        }
        sum0 += __shfl_xor_sync(0xFFFFFFFFu, sum0, 1);
        sum0 += __shfl_xor_sync(0xFFFFFFFFu, sum0, 2);
        sum1 += __shfl_xor_sync(0xFFFFFFFFu, sum1, 1);
        sum1 += __shfl_xor_sync(0xFFFFFFFFu, sum1, 2);
        l0 = l0 * a0 + sum0;
        l1 = l1 * a1 + sum1;

        #pragma unroll
        for (int dt = 0; dt < 8; dt++) {
            o[dt][0] *= a0; o[dt][1] *= a0;
            o[dt][2] *= a1; o[dt][3] *= a1;
        }

        // ---- P -> bf16 hi/lo A-frags ----
        uint32_t ph[4][4], pl[4][4];
        #pragma unroll
        for (int kg = 0; kg < 4; kg++) {
            pack_split(s[2 * kg][0], s[2 * kg][1], ph[kg][0], pl[kg][0]);
            pack_split(s[2 * kg][2], s[2 * kg][3], ph[kg][1], pl[kg][1]);
            pack_split(s[2 * kg + 1][0], s[2 * kg + 1][1], ph[kg][2], pl[kg][2]);
            pack_split(s[2 * kg + 1][2], s[2 * kg + 1][3], ph[kg][3], pl[kg][3]);
        }

        // ---- O += P V (hi/lo 3-term) ----
        #pragma unroll
        for (int kg = 0; kg < 4; kg++) {
            #pragma unroll
            for (int dg = 0; dg < 4; dg++) {
                uint32_t vh4[4], vl4[4];
                const uint32_t o2 = (uint32_t)(kg * 16 * AST + dg * 16) * 2;
                ldsm4t(vh4, vA + o2);
                ldsm4t(vl4, vA + LOFS + o2);
                mma16816(o[2 * dg], ph[kg][0], ph[kg][1], ph[kg][2], ph[kg][3], vh4[0], vh4[1]);
                mma16816(o[2 * dg], ph[kg][0], ph[kg][1], ph[kg][2], ph[kg][3], vl4[0], vl4[1]);
                mma16816(o[2 * dg], pl[kg][0], pl[kg][1], pl[kg][2], pl[kg][3], vh4[0], vh4[1]);
                mma16816(o[2 * dg + 1], ph[kg][0], ph[kg][1], ph[kg][2], ph[kg][3], vh4[2], vh4[3]);
                mma16816(o[2 * dg + 1], ph[kg][0], ph[kg][1], ph[kg][2], ph[kg][3], vl4[2], vl4[3]);
                mma16816(o[2 * dg + 1], pl[kg][0], pl[kg][1], pl[kg][2], pl[kg][3], vh4[2], vh4[3]);
            }
        }
        __syncthreads();
    }

    // ---- store UNNORMALIZED partial + (m, l) per row ----
    const size_t r_lo = qrow0 + wid * 16 + (lane >> 2);
    const size_t r_hi = r_lo + 8;
    #pragma unroll
    for (int dt = 0; dt < 8; dt++) {
        const int c = h * DD + dt * 8 + 2 * (lane & 3);
        *(float2*)(pO + r_lo * CC + c) = make_float2(o[dt][0], o[dt][1]);
        *(float2*)(pO + r_hi * CC + c) = make_float2(o[dt][2], o[dt][3]);
    }
    if ((lane & 3) == 0) {
        pM[(size_t)h * ROWS + r_lo] = m0;
        pL[(size_t)h * ROWS + r_lo] = l0;
        pM[(size_t)h * ROWS + r_hi] = m1;
        pL[(size_t)h * ROWS + r_hi] = l1;
    }
}

// ---------------------------------------------------------------------------
// Merge the two KV-half partials into O (bf16 hi/lo split).
// One thread handles 8 consecutive d-columns of one (row, head).
// total threads = ROWS * HH * (DD/8) = 393216 -> 1536 blocks x 256.
// ---------------------------------------------------------------------------
__global__ __launch_bounds__(256) void merge_attn()
{
    const int t = blockIdx.x * blockDim.x + threadIdx.x;   // 0 .. 393215
    const int g = t & 7;                 // col group within head
    const int rh = t >> 3;               // 0 .. ROWS*HH-1
    const int gr = rh & (ROWS - 1);      // global row (ROWS = 4096 pow2)
    const int h = rh >> 12;              // rh / ROWS

    const size_t mi = (size_t)h * ROWS + gr;
    const float m0 = g_m0a[mi], l0 = g_l0a[mi];
    const float m1 = g_m1a[mi], l1 = g_l1a[mi];
    const float mm = fmaxf(m0, m1);
    const float a0 = __expf(m0 - mm), a1 = __expf(m1 - mm);
    const float inv = 1.0f / (l0 * a0 + l1 * a1);
    const float f0 = a0 * inv, f1 = a1 * inv;

    const size_t base = (size_t)gr * CC + h * DD + g * 8;
    const float4 p0a = *(const float4*)(g_p0 + base);
    const float4 p0b = *(const float4*)(g_p0 + base + 4);
    const float4 p1a = *(const float4*)(g_p1 + base);
    const float4 p1b = *(const float4*)(g_p1 + base + 4);

    split_store(g_oh, g_ol, base + 0, p0a.x * f0 + p1a.x * f1, p0a.y * f0 + p1a.y * f1);
    split_store(g_oh, g_ol, base + 2, p0a.z * f0 + p1a.z * f1, p0a.w * f0 + p1a.w * f1);
    split_store(g_oh, g_ol, base + 4, p0b.x * f0 + p1b.x * f1, p0b.y * f0 + p1b.y * f1);
    split_store(g_oh, g_ol, base + 6, p0b.z * f0 + p1b.z * f1, p0b.w * f0 + p1b.w * f1);
}

// ---------------------------------------------------------------------------
// Launch
// ---------------------------------------------------------------------------
extern "C" void kernel_launch(void* const* d_in, const int* in_sizes, int n_in,
                              void* d_out, int out_size)
{
    const float* x  = (const float*)d_in[0];
    const float* y  = (const float*)d_in[1];
    const float* yw = (const float*)d_in[2];
    const float* Wq = (const float*)d_in[3];
    const float* Wk = (const float*)d_in[4];
    const float* Wv = (const float*)d_in[5];
    const float* Wp = (const float*)d_in[6];
    const float* bp = (const float*)d_in[7];
    float* out = (float*)d_out;

    cudaFuncSetAttribute(gemm_all<false>,
                         cudaFuncAttributeMaxDynamicSharedMemorySize, GEMM_SMEM);
    cudaFuncSetAttribute(gemm_all<true>,
                         cudaFuncAttributeMaxDynamicSharedMemorySize, GEMM_SMEM);
    cudaFuncSetAttribute(attn_ms,
                         cudaFuncAttributeMaxDynamicSharedMemorySize, ATT_SMEM2);

    // Fused hi/lo conversion of all inputs + tile-counter reset
    cvt_all<<<2112, 256>>>((const float4*)x, (const float4*)y,
                           (const float4*)Wq, (const float4*)Wk,
                           (const float4*)Wv, (const float4*)Wp);

    // Q/K/V projections: persistent, double-buffered, dynamic tiles
    gemm_all<false><<<GEMM_GRID, 256, GEMM_SMEM>>>(yw, nullptr, nullptr);

    // Split-KV attention: 768 uniform CTAs (z = key half)
    attn_ms<<<dim3(NN / 128, NB * HH, 2), 256, ATT_SMEM2>>>();

    // Merge partials into O (bf16 hi/lo)
    merge_attn<<<1536, 256>>>();

    // Output projection: out = O Wp^T + bp
    gemm_all<true><<<GEMM_GRID, 256, GEMM_SMEM>>>(nullptr, bp, out);
}

// round 16
// speedup vs baseline: 1.0226x; 1.0226x over previous
#include <cuda_runtime.h>
#include <cuda_bf16.h>
#include <cstdint>

// Problem constants
#define NB 4
#define NN 1024
#define MM 1024
#define CC 768
#define HH 12
#define DD 64
#define ROWS (NB * NN)        // 4096
#define ATT_SCALE 0.125f      // 64^-0.5 (exact power of two)

// ---------------------------------------------------------------------------
// Scratch (static device arrays — allocation-free per harness rules)
// ---------------------------------------------------------------------------
__device__ __nv_bfloat16 g_xh[ROWS * CC], g_xl[ROWS * CC];
__device__ __nv_bfloat16 g_yh[ROWS * CC], g_yl[ROWS * CC];
__device__ __nv_bfloat16 g_qh[ROWS * CC], g_ql[ROWS * CC];   // pre-scaled by 0.125
__device__ __nv_bfloat16 g_kh[ROWS * CC], g_kl[ROWS * CC];
__device__ __nv_bfloat16 g_vh[ROWS * CC], g_vl[ROWS * CC];
__device__ __nv_bfloat16 g_oh[ROWS * CC], g_ol[ROWS * CC];
__device__ __nv_bfloat16 g_wqh[CC * CC], g_wql[CC * CC];
__device__ __nv_bfloat16 g_wkh[CC * CC], g_wkl[CC * CC];
__device__ __nv_bfloat16 g_wvh[CC * CC], g_wvl[CC * CC];
__device__ __nv_bfloat16 g_wph[CC * CC], g_wpl[CC * CC];

// Dynamic tile counters (reset by cvt_all each launch/replay)
__device__ int g_ctrP;
__device__ int g_ctrO;

// ---------------------------------------------------------------------------
// Helpers
// ---------------------------------------------------------------------------
__device__ __forceinline__ uint32_t smem_u32(const void* p) {
    uint32_t a;
    asm("{ .reg .u64 t; cvta.to.shared.u64 t, %1; cvt.u32.u64 %0, t; }"
        : "=r"(a) : "l"(p));
    return a;
}

__device__ __forceinline__ void mma16816(float d[4],
    uint32_t a0, uint32_t a1, uint32_t a2, uint32_t a3,
    uint32_t b0, uint32_t b1)
{
    asm volatile(
        "mma.sync.aligned.m16n8k16.row.col.f32.bf16.bf16.f32 "
        "{%0,%1,%2,%3}, {%4,%5,%6,%7}, {%8,%9}, {%0,%1,%2,%3};"
        : "+f"(d[0]), "+f"(d[1]), "+f"(d[2]), "+f"(d[3])
        : "r"(a0), "r"(a1), "r"(a2), "r"(a3), "r"(b0), "r"(b1));
}

__device__ __forceinline__ void ldsm4(uint32_t r[4], uint32_t addr) {
    asm volatile("ldmatrix.sync.aligned.m8n8.x4.shared.b16 {%0,%1,%2,%3}, [%4];"
                 : "=r"(r[0]), "=r"(r[1]), "=r"(r[2]), "=r"(r[3]) : "r"(addr));
}
__device__ __forceinline__ void ldsm4t(uint32_t r[4], uint32_t addr) {
    asm volatile("ldmatrix.sync.aligned.m8n8.x4.trans.shared.b16 {%0,%1,%2,%3}, [%4];"
                 : "=r"(r[0]), "=r"(r[1]), "=r"(r[2]), "=r"(r[3]) : "r"(addr));
}

__device__ __forceinline__ void cp16(uint32_t smem_dst, const void* gsrc) {
    asm volatile("cp.async.cg.shared.global [%0], [%1], 16;"
                 :: "r"(smem_dst), "l"(gsrc));
}
#define CP_COMMIT() asm volatile("cp.async.commit_group;" ::: "memory")
#define CP_WAIT0()  asm volatile("cp.async.wait_group 0;" ::: "memory")
#define CP_WAIT1()  asm volatile("cp.async.wait_group 1;" ::: "memory")

// Split two fp32 into packed bf16-hi (truncation) + bf16-lo (rounded residual)
__device__ __forceinline__ void pack_split(float v0, float v1,
                                           uint32_t& hp, uint32_t& lp)
{
    const uint32_t u0 = __float_as_uint(v0), u1 = __float_as_uint(v1);
    hp = __byte_perm(u0, u1, 0x7632);
    const float r0 = v0 - __uint_as_float(u0 & 0xFFFF0000u);
    const float r1 = v1 - __uint_as_float(u1 & 0xFFFF0000u);
    __nv_bfloat162 t = __floats2bfloat162_rn(r0, r1);
    lp = *reinterpret_cast<uint32_t*>(&t);
}

__device__ __forceinline__ void split_store(__nv_bfloat16* H, __nv_bfloat16* L,
                                            size_t off, float v0, float v1)
{
    uint32_t hp, lp;
    pack_split(v0, v1, hp, lp);
    *reinterpret_cast<uint32_t*>(H + off) = hp;
    *reinterpret_cast<uint32_t*>(L + off) = lp;
}

// ---------------------------------------------------------------------------
// Fused fp32 -> bf16 hi/lo split for all six source arrays (+ counter reset)
// ---------------------------------------------------------------------------
#define A4 (ROWS * CC / 4)     // 786432 quads per activation
#define W4 (CC * CC / 4)       // 147456 quads per weight
#define CVT_TOTAL (2 * A4 + 4 * W4)

__global__ __launch_bounds__(256) void cvt_all(
    const float4* __restrict__ x, const float4* __restrict__ y,
    const float4* __restrict__ wq, const float4* __restrict__ wk,
    const float4* __restrict__ wv, const float4* __restrict__ wp)
{
    if (blockIdx.x == 0 && threadIdx.x == 0) { g_ctrP = 0; g_ctrO = 0; }

    int i = blockIdx.x * blockDim.x + threadIdx.x;
    const int stride = gridDim.x * blockDim.x;
    for (; i < CVT_TOTAL; i += stride) {
        const float4* s;
        uint2 *h, *l;
        int j;
        if (i < A4)            { s = x; h = (uint2*)g_xh; l = (uint2*)g_xl; j = i; }
        else if (i < 2 * A4)   { s = y; h = (uint2*)g_yh; l = (uint2*)g_yl; j = i - A4; }
        else {
            const int t = i - 2 * A4;
            const int w = t / W4;
            j = t - w * W4;
            if (w == 0)      { s = wq; h = (uint2*)g_wqh; l = (uint2*)g_wql; }
            else if (w == 1) { s = wk; h = (uint2*)g_wkh; l = (uint2*)g_wkl; }
            else if (w == 2) { s = wv; h = (uint2*)g_wvh; l = (uint2*)g_wvl; }
            else             { s = wp; h = (uint2*)g_wph; l = (uint2*)g_wpl; }
        }
        const float4 v = s[j];
        uint32_t h0, l0, h1, l1;
        pack_split(v.x, v.y, h0, l0);
        pack_split(v.z, v.w, h1, l1);
        h[j] = make_uint2(h0, h1);
        l[j] = make_uint2(l0, l1);
    }
}

// ---------------------------------------------------------------------------
// Persistent mma.sync NT GEMM (R13 winner config, frozen):
// bf16 hi/lo, tile 128x64, BK=64, 2-stage cp.async double buffer,
// 256 threads (8 warps, 2m x 4n), warp tile 64x16, 2 CTAs/SM, tile stealing.
// ---------------------------------------------------------------------------
#define GST 72                         // padded row stride (elems), 144B
#define GTA (128 * GST)                // A tile elems (hi or lo)
#define GTB (64 * GST)                 // B tile elems (hi or lo)
#define GSTG (2 * GTA + 2 * GTB)       // elems per stage = 27648
#define GEMM_SMEM (2 * GSTG * 2)       // 110592 bytes
#define KSTEPS (CC / 64)               // 12
#define TILES_PER_MAT (32 * 12)        // 384
#define NT_PROJ (3 * TILES_PER_MAT)    // 1152
#define NT_OPROJ TILES_PER_MAT         // 384
#define GEMM_GRID 296                  // 2 per SM x 148

template <bool OPROJ>
__global__ __launch_bounds__(256, 2) void gemm_all(
    const float* __restrict__ rowbias,   // yw (proj) / nullptr
    const float* __restrict__ colbias,   // nullptr / bp
    float* __restrict__ outF)            // nullptr / out
{
    extern __shared__ char sm[];
    const uint32_t sbase = smem_u32(sm);
    __shared__ int s_tile;

    const int tid = threadIdx.x;
    const int wid = tid >> 5, lane = tid & 31;
    const int wm = wid >> 2, wn = wid & 3;          // 2 x 4 warp grid
    const int lrow = lane & 15, lcol = (lane >> 4) * 8;
    const int NT = OPROJ ? NT_OPROJ : NT_PROJ;

    for (;;) {
        if (tid == 0)
            s_tile = atomicAdd(OPROJ ? &g_ctrO : &g_ctrP, 1);
        __syncthreads();
        const int t = s_tile;
        if (t >= NT) break;

        const int z = OPROJ ? 3 : (t / TILES_PER_MAT);
        const int rem = OPROJ ? t : (t - z * TILES_PER_MAT);
        const int row0 = (rem & 31) * 128;
        const int col0 = (rem >> 5) * 64;

        const __nv_bfloat16 *Ah, *Al, *Bh, *Bl;
        __nv_bfloat16 *OH = nullptr, *OL = nullptr;
        if (OPROJ) {
            Ah = g_oh; Al = g_ol; Bh = g_wph; Bl = g_wpl;
        } else if (z == 0) {
            Ah = g_xh; Al = g_xl; Bh = g_wqh; Bl = g_wql; OH = g_qh; OL = g_ql;
        } else if (z == 1) {
            Ah = g_yh; Al = g_yl; Bh = g_wkh; Bl = g_wkl; OH = g_kh; OL = g_kl;
        } else {
            Ah = g_yh; Al = g_yl; Bh = g_wvh; Bl = g_wvl; OH = g_vh; OL = g_vl;
        }

        float acc[4][2][4];
        #pragma unroll
        for (int i = 0; i < 4; i++)
            #pragma unroll
            for (int j = 0; j < 2; j++)
                #pragma unroll
                for (int e = 0; e < 4; e++) acc[i][j][e] = 0.0f;

        auto stage_load = [&](int st, int stage) {
            const int k0 = st * 64;
            #pragma unroll
            for (int j = 0; j < 12; j++) {
                const int ch = tid + j * 256;
                const __nv_bfloat16* src;
                uint32_t soff;
                int r, c;
                if (ch < 1024) {
                    r = ch >> 3; c = ch & 7;
                    src = Ah + (size_t)(row0 + r) * CC;
                    soff = (uint32_t)(r * GST + c * 8);
                } else if (ch < 2048) {
                    const int q = ch - 1024; r = q >> 3; c = q & 7;
                    src = Al + (size_t)(row0 + r) * CC;
                    soff = (uint32_t)(GTA + r * GST + c * 8);
                } else if (ch < 2560) {
                    const int q = ch - 2048; r = q >> 3; c = q & 7;
                    src = Bh + (size_t)(col0 + r) * CC;
                    soff = (uint32_t)(2 * GTA + r * GST + c * 8);
                } else {
                    const int q = ch - 2560; r = q >> 3; c = q & 7;
                    src = Bl + (size_t)(col0 + r) * CC;
                    soff = (uint32_t)(2 * GTA + GTB + r * GST + c * 8);
                }
                cp16(sbase + (uint32_t)(stage * GSTG) * 2 + soff * 2,
                     src + k0 + c * 8);
            }
            CP_COMMIT();
        };

        stage_load(0, 0);

        for (int st = 0; st < KSTEPS; st++) {
            const int buf = st & 1;
            if (st + 1 < KSTEPS) {
                stage_load(st + 1, buf ^ 1);
                CP_WAIT1();
            } else {
                CP_WAIT0();
            }
            __syncthreads();

            const uint32_t Ab = sbase + (uint32_t)(buf * GSTG) * 2 +
                                (uint32_t)((wm * 64 + lrow) * GST + lcol) * 2;
            const uint32_t Bb = sbase + (uint32_t)(buf * GSTG + 2 * GTA) * 2 +
                                (uint32_t)((wn * 16 + lrow) * GST + lcol) * 2;

            #pragma unroll
            for (int kk = 0; kk < 4; kk++) {
                uint32_t afh[4][4], afl[4][4];
                #pragma unroll
                for (int mt = 0; mt < 4; mt++) {
                    const uint32_t o2 = (uint32_t)(mt * 16 * GST + kk * 16) * 2;
                    ldsm4(afh[mt], Ab + o2);
                    ldsm4(afl[mt], Ab + (uint32_t)GTA * 2 + o2);
                }
                uint32_t bh[4], bl[4];
                const uint32_t o2 = (uint32_t)(kk * 16) * 2;
                ldsm4(bh, Bb + o2);
                ldsm4(bl, Bb + (uint32_t)GTB * 2 + o2);
                #pragma unroll
                for (int mt = 0; mt < 4; mt++) {
                    mma16816(acc[mt][0], afh[mt][0], afh[mt][1], afh[mt][2], afh[mt][3], bh[0], bh[2]);
                    mma16816(acc[mt][0], afh[mt][0], afh[mt][1], afh[mt][2], afh[mt][3], bl[0], bl[2]);
                    mma16816(acc[mt][0], afl[mt][0], afl[mt][1], afl[mt][2], afl[mt][3], bh[0], bh[2]);
                    mma16816(acc[mt][1], afh[mt][0], afh[mt][1], afh[mt][2], afh[mt][3], bh[1], bh[3]);
                    mma16816(acc[mt][1], afh[mt][0], afh[mt][1], afh[mt][2], afh[mt][3], bl[1], bl[3]);
                    mma16816(acc[mt][1], afl[mt][0], afl[mt][1], afl[mt][2], afl[mt][3], bh[1], bh[3]);
                }
            }
            __syncthreads();
        }

        // Epilogue
        const float scale = (!OPROJ && z == 0) ? ATT_SCALE : 1.0f;
        #pragma unroll
        for (int mt = 0; mt < 4; mt++) {
            const int r_lo = row0 + wm * 64 + mt * 16 + (lane >> 2);
            const int r_hi = r_lo + 8;
            const float rb_lo = (!OPROJ && z == 1) ? rowbias[r_lo] : 0.0f;
            const float rb_hi = (!OPROJ && z == 1) ? rowbias[r_hi] : 0.0f;
            #pragma unroll
            for (int nt = 0; nt < 2; nt++) {
                const int c = col0 + wn * 16 + nt * 8 + 2 * (lane & 3);
                const float cb0 = OPROJ ? colbias[c] : 0.0f;
                const float cb1 = OPROJ ? colbias[c + 1] : 0.0f;
                const float v0 = acc[mt][nt][0] * scale + rb_lo + cb0;
                const float v1 = acc[mt][nt][1] * scale + rb_lo + cb1;
                const float v2 = acc[mt][nt][2] * scale + rb_hi + cb0;
                const float v3 = acc[mt][nt][3] * scale + rb_hi + cb1;
                if (OPROJ) {
                    *(float2*)(outF + (size_t)r_lo * CC + c) = make_float2(v0, v1);
                    *(float2*)(outF + (size_t)r_hi * CC + c) = make_float2(v2, v3);
                } else {
                    split_store(OH, OL, (size_t)r_lo * CC + c, v0, v1);
                    split_store(OH, OL, (size_t)r_hi * CC + c, v2, v3);
                }
            }
        }
        __syncthreads();
    }
}

// ---------------------------------------------------------------------------
// Flash attention (mma.sync, bf16 hi/lo), cp.async double-buffered K/V.
// 64 q-rows per CTA, 128 threads (4 warps x 16 rows), full 1024-key sweep,
// softmax-complete per CTA (no merge). grid (NN/64, NB*HH) = 768 CTAs,
// 3 CTAs/SM (73.7 KB smem each). Q staged through KV stage 0.
// Q is pre-scaled by ATT_SCALE at projection time.
// ---------------------------------------------------------------------------
#define AST 72
#define KVT (64 * AST)                 // 4608 elems
#define KVSTG (4 * KVT)                // 18432 elems per stage
#define ATT_SMEM2 (2 * KVSTG * 2)      // 73728 bytes
#define NKV (MM / 64)                  // 16

__global__ __launch_bounds__(128, 3) void attn_ms()
{
    extern __shared__ char sm[];
    const uint32_t sbase = smem_u32(sm);

    const int tid = threadIdx.x;
    const int wid = tid >> 5, lane = tid & 31;
    const int lrow = lane & 15, lcol = (lane >> 4) * 8;
    const int n0 = blockIdx.x * 64;
    const int b = blockIdx.y / HH, h = blockIdx.y % HH;
    const size_t qrow0 = (size_t)(b * NN + n0);
    const size_t kvrow0 = (size_t)(b * MM);

    const int qa = tid >> 6;                    // 0..1 : qh / ql
    const __nv_bfloat16* qsrc = qa ? g_ql : g_qh;
    const int ka = tid >> 5;                    // 0..3 : kh, kl, vh, vl (warp per array)
    const __nv_bfloat16* ksrc = (ka == 0) ? g_kh : (ka == 1) ? g_kl
                              : (ka == 2) ? g_vh : g_vl;

    auto kv_load = [&](int m0i, int stage) {
        #pragma unroll
        for (int j = 0; j < 16; j++) {
            const int ch = (tid & 31) + j * 32;    // 0..511 per array
            const int r = ch >> 3, c = ch & 7;
            cp16(sbase + (uint32_t)(stage * KVSTG + ka * KVT + r * AST + c * 8) * 2,
                 ksrc + (kvrow0 + m0i + r) * CC + h * DD + c * 8);
        }
        CP_COMMIT();
    };

    // ---- Q (64 rows, hi+lo) through stage 0: load, extract frags, release ----
    #pragma unroll
    for (int j = 0; j < 8; j++) {
        const int ch = (tid & 63) + j * 64;        // 0..511 per array
        const int r = ch >> 3, c = ch & 7;
        cp16(sbase + (uint32_t)(qa * 64 * AST + r * AST + c * 8) * 2,
             qsrc + (qrow0 + r) * CC + h * DD + c * 8);
    }
    CP_COMMIT();
    CP_WAIT0();
    __syncthreads();

    uint32_t qfh[4][4], qfl[4][4];
    {
        const uint32_t qb = sbase + (uint32_t)((wid * 16 + lrow) * AST + lcol) * 2;
        #pragma unroll
        for (int kk = 0; kk < 4; kk++) {
            ldsm4(qfh[kk], qb + kk * 32);
            ldsm4(qfl[kk], qb + (uint32_t)(64 * AST) * 2 + kk * 32);
        }
    }
    __syncthreads();    // all warps done reading Q before stage 0 is reused

    kv_load(0, 0);

    float m0 = -1e30f, m1 = -1e30f, l0 = 0.0f, l1 = 0.0f;
    float o[8][4];
    #pragma unroll
    for (int dt = 0; dt < 8; dt++)
        #pragma unroll
        for (int e = 0; e < 4; e++) o[dt][e] = 0.0f;

    for (int st = 0; st < NKV; st++) {
        const int buf = st & 1;
        if (st + 1 < NKV) {
            kv_load((st + 1) * 64, buf ^ 1);
            CP_WAIT1();
        } else {
            CP_WAIT0();
        }
        __syncthreads();

        const uint32_t kvb = sbase + (uint32_t)(buf * KVSTG) * 2;
        const uint32_t kA = kvb + (uint32_t)(lrow * AST + lcol) * 2;
        const uint32_t vA = kvb + (uint32_t)(2 * KVT + lrow * AST + lcol) * 2;
        const uint32_t LOFS = (uint32_t)KVT * 2;

        // ---- S = Q K^T (hi/lo 3-term), Q pre-scaled ----
        float s[8][4];
        #pragma unroll
        for (int nt = 0; nt < 8; nt++)
            #pragma unroll
            for (int e = 0; e < 4; e++) s[nt][e] = 0.0f;

        #pragma unroll
        for (int kg = 0; kg < 4; kg++) {
            #pragma unroll
            for (int kk = 0; kk < 4; kk++) {
                uint32_t bh[4], bl[4];
                const uint32_t o2 = (uint32_t)(kg * 16 * AST + kk * 16) * 2;
                ldsm4(bh, kA + o2);
                ldsm4(bl, kA + LOFS + o2);
                mma16816(s[2 * kg], qfh[kk][0], qfh[kk][1], qfh[kk][2], qfh[kk][3], bh[0], bh[2]);
                mma16816(s[2 * kg], qfh[kk][0], qfh[kk][1], qfh[kk][2], qfh[kk][3], bl[0], bl[2]);
                mma16816(s[2 * kg], qfl[kk][0], qfl[kk][1], qfl[kk][2], qfl[kk][3], bh[0], bh[2]);
                mma16816(s[2 * kg + 1], qfh[kk][0], qfh[kk][1], qfh[kk][2], qfh[kk][3], bh[1], bh[3]);
                mma16816(s[2 * kg + 1], qfh[kk][0], qfh[kk][1], qfh[kk][2], qfh[kk][3], bl[1], bl[3]);
                mma16816(s[2 * kg + 1], qfl[kk][0], qfl[kk][1], qfl[kk][2], qfl[kk][3], bh[1], bh[3]);
            }
        }

        // ---- online softmax ----
        float mx0 = -1e30f, mx1 = -1e30f;
        #pragma unroll
        for (int nt = 0; nt < 8; nt++) {
            mx0 = fmaxf(mx0, fmaxf(s[nt][0], s[nt][1]));
            mx1 = fmaxf(mx1, fmaxf(s[nt][2], s[nt][3]));
        }
        mx0 = fmaxf(mx0, __shfl_xor_sync(0xFFFFFFFFu, mx0, 1));
        mx0 = fmaxf(mx0, __shfl_xor_sync(0xFFFFFFFFu, mx0, 2));
        mx1 = fmaxf(mx1, __shfl_xor_sync(0xFFFFFFFFu, mx1, 1));
        mx1 = fmaxf(mx1, __shfl_xor_sync(0xFFFFFFFFu, mx1, 2));

        const float mn0 = fmaxf(m0, mx0), mn1 = fmaxf(m1, mx1);
        const float a0 = __expf(m0 - mn0), a1 = __expf(m1 - mn1);
        m0 = mn0; m1 = mn1;

        float sum0 = 0.0f, sum1 = 0.0f;
        #pragma unroll
        for (int nt = 0; nt < 8; nt++) {
            s[nt][0] = __expf(s[nt][0] - mn0); sum0 += s[nt][0];
            s[nt][1] = __expf(s[nt][1] - mn0); sum0 += s[nt][1];
            s[nt][2] = __expf(s[nt][2] - mn1); sum1 += s[nt][2];
            s[nt][3] = __expf(s[nt][3] - mn1); sum1 += s[nt][3];
        }
        sum0 += __shfl_xor_sync(0xFFFFFFFFu, sum0, 1);
        sum0 += __shfl_xor_sync(0xFFFFFFFFu, sum0, 2);
        sum1 += __shfl_xor_sync(0xFFFFFFFFu, sum1, 1);
        sum1 += __shfl_xor_sync(0xFFFFFFFFu, sum1, 2);
        l0 = l0 * a0 + sum0;
        l1 = l1 * a1 + sum1;

        #pragma unroll
        for (int dt = 0; dt < 8; dt++) {
            o[dt][0] *= a0; o[dt][1] *= a0;
            o[dt][2] *= a1; o[dt][3] *= a1;
        }

        // ---- P -> bf16 hi/lo A-frags ----
        uint32_t ph[4][4], pl[4][4];
        #pragma unroll
        for (int kg = 0; kg < 4; kg++) {
            pack_split(s[2 * kg][0], s[2 * kg][1], ph[kg][0], pl[kg][0]);
            pack_split(s[2 * kg][2], s[2 * kg][3], ph[kg][1], pl[kg][1]);
            pack_split(s[2 * kg + 1][0], s[2 * kg + 1][1], ph[kg][2], pl[kg][2]);
            pack_split(s[2 * kg + 1][2], s[2 * kg + 1][3], ph[kg][3], pl[kg][3]);
        }

        // ---- O += P V (hi/lo 3-term) ----
        #pragma unroll
        for (int kg = 0; kg < 4; kg++) {
            #pragma unroll
            for (int dg = 0; dg < 4; dg++) {
                uint32_t vh4[4], vl4[4];
                const uint32_t o2 = (uint32_t)(kg * 16 * AST + dg * 16) * 2;
                ldsm4t(vh4, vA + o2);
                ldsm4t(vl4, vA + LOFS + o2);
                mma16816(o[2 * dg], ph[kg][0], ph[kg][1], ph[kg][2], ph[kg][3], vh4[0], vh4[1]);
                mma16816(o[2 * dg], ph[kg][0], ph[kg][1], ph[kg][2], ph[kg][3], vl4[0], vl4[1]);
                mma16816(o[2 * dg], pl[kg][0], pl[kg][1], pl[kg][2], pl[kg][3], vh4[0], vh4[1]);
                mma16816(o[2 * dg + 1], ph[kg][0], ph[kg][1], ph[kg][2], ph[kg][3], vh4[2], vh4[3]);
                mma16816(o[2 * dg + 1], ph[kg][0], ph[kg][1], ph[kg][2], ph[kg][3], vl4[2], vl4[3]);
                mma16816(o[2 * dg + 1], pl[kg][0], pl[kg][1], pl[kg][2], pl[kg][3], vh4[2], vh4[3]);
            }
        }
        __syncthreads();
    }

    // ---- normalize + split-store O ----
    const float inv0 = 1.0f / l0, inv1 = 1.0f / l1;
    const size_t r_lo = qrow0 + wid * 16 + (lane >> 2);
    const size_t r_hi = r_lo + 8;
    #pragma unroll
    for (int dt = 0; dt < 8; dt++) {
        const int c = h * DD + dt * 8 + 2 * (lane & 3);
        split_store(g_oh, g_ol, r_lo * CC + c, o[dt][0] * inv0, o[dt][1] * inv0);
        split_store(g_oh, g_ol, r_hi * CC + c, o[dt][2] * inv1, o[dt][3] * inv1);
    }
}

// ---------------------------------------------------------------------------
// Launch
// ---------------------------------------------------------------------------
extern "C" void kernel_launch(void* const* d_in, const int* in_sizes, int n_in,
                              void* d_out, int out_size)
{
    const float* x  = (const float*)d_in[0];
    const float* y  = (const float*)d_in[1];
    const float* yw = (const float*)d_in[2];
    const float* Wq = (const float*)d_in[3];
    const float* Wk = (const float*)d_in[4];
    const float* Wv = (const float*)d_in[5];
    const float* Wp = (const float*)d_in[6];
    const float* bp = (const float*)d_in[7];
    float* out = (float*)d_out;

    cudaFuncSetAttribute(gemm_all<false>,
                         cudaFuncAttributeMaxDynamicSharedMemorySize, GEMM_SMEM);
    cudaFuncSetAttribute(gemm_all<true>,
                         cudaFuncAttributeMaxDynamicSharedMemorySize, GEMM_SMEM);
    cudaFuncSetAttribute(attn_ms,
                         cudaFuncAttributeMaxDynamicSharedMemorySize, ATT_SMEM2);

    // Fused hi/lo conversion of all inputs + tile-counter reset
    cvt_all<<<2112, 256>>>((const float4*)x, (const float4*)y,
                           (const float4*)Wq, (const float4*)Wk,
                           (const float4*)Wv, (const float4*)Wp);

    // Q/K/V projections: persistent, double-buffered, dynamic tiles
    gemm_all<false><<<GEMM_GRID, 256, GEMM_SMEM>>>(yw, nullptr, nullptr);

    // Attention: 64 q-rows/CTA, 768 CTAs, 3 CTAs/SM, softmax-complete
    attn_ms<<<dim3(NN / 64, NB * HH), 128, ATT_SMEM2>>>();

    // Output projection: out = O Wp^T + bp
    gemm_all<true><<<GEMM_GRID, 256, GEMM_SMEM>>>(nullptr, bp, out);
}

// round 17
// speedup vs baseline: 1.0815x; 1.0576x over previous
#include <cuda_runtime.h>
#include <cuda_fp16.h>
#include <cstdint>

// Problem constants
#define NB 4
#define NN 1024
#define MM 1024
#define CC 768
#define HH 12
#define DD 64
#define ROWS (NB * NN)        // 4096
#define ATT_SCALE 0.125f      // 64^-0.5 (exact power of two)

// ---------------------------------------------------------------------------
// Scratch (static device arrays — allocation-free per harness rules)
// fp16 hi/lo pairs (pair error ~2^-22); O is SINGLE fp16 (oproj is 2-term).
// ---------------------------------------------------------------------------
__device__ __half g_xh[ROWS * CC], g_xl[ROWS * CC];
__device__ __half g_yh[ROWS * CC], g_yl[ROWS * CC];
__device__ __half g_qh[ROWS * CC], g_ql[ROWS * CC];   // pre-scaled by 0.125
__device__ __half g_kh[ROWS * CC], g_kl[ROWS * CC];
__device__ __half g_vh[ROWS * CC], g_vl[ROWS * CC];
__device__ __half g_oh[ROWS * CC];                    // single fp16 (rn)
__device__ __half g_wqh[CC * CC], g_wql[CC * CC];
__device__ __half g_wkh[CC * CC], g_wkl[CC * CC];
__device__ __half g_wvh[CC * CC], g_wvl[CC * CC];
__device__ __half g_wph[CC * CC], g_wpl[CC * CC];

// Dynamic tile counters (reset by cvt_all each launch/replay)
__device__ int g_ctrP;
__device__ int g_ctrO;

// ---------------------------------------------------------------------------
// Helpers
// ---------------------------------------------------------------------------
__device__ __forceinline__ uint32_t smem_u32(const void* p) {
    uint32_t a;
    asm("{ .reg .u64 t; cvta.to.shared.u64 t, %1; cvt.u32.u64 %0, t; }"
        : "=r"(a) : "l"(p));
    return a;
}

// D += A * B  (m16n8k16, fp16 in, fp32 accum)
__device__ __forceinline__ void mma16816(float d[4],
    uint32_t a0, uint32_t a1, uint32_t a2, uint32_t a3,
    uint32_t b0, uint32_t b1)
{
    asm volatile(
        "mma.sync.aligned.m16n8k16.row.col.f32.f16.f16.f32 "
        "{%0,%1,%2,%3}, {%4,%5,%6,%7}, {%8,%9}, {%0,%1,%2,%3};"
        : "+f"(d[0]), "+f"(d[1]), "+f"(d[2]), "+f"(d[3])
        : "r"(a0), "r"(a1), "r"(a2), "r"(a3), "r"(b0), "r"(b1));
}

__device__ __forceinline__ void ldsm4(uint32_t r[4], uint32_t addr) {
    asm volatile("ldmatrix.sync.aligned.m8n8.x4.shared.b16 {%0,%1,%2,%3}, [%4];"
                 : "=r"(r[0]), "=r"(r[1]), "=r"(r[2]), "=r"(r[3]) : "r"(addr));
}
__device__ __forceinline__ void ldsm4t(uint32_t r[4], uint32_t addr) {
    asm volatile("ldmatrix.sync.aligned.m8n8.x4.trans.shared.b16 {%0,%1,%2,%3}, [%4];"
                 : "=r"(r[0]), "=r"(r[1]), "=r"(r[2]), "=r"(r[3]) : "r"(addr));
}

__device__ __forceinline__ void cp16(uint32_t smem_dst, const void* gsrc) {
    asm volatile("cp.async.cg.shared.global [%0], [%1], 16;"
                 :: "r"(smem_dst), "l"(gsrc));
}
#define CP_COMMIT() asm volatile("cp.async.commit_group;" ::: "memory")
#define CP_WAIT0()  asm volatile("cp.async.wait_group 0;" ::: "memory")
#define CP_WAIT1()  asm volatile("cp.async.wait_group 1;" ::: "memory")

// Split two fp32 into packed fp16-hi (rn) + fp16-lo (rn residual)
__device__ __forceinline__ void pack_split(float v0, float v1,
                                           uint32_t& hp, uint32_t& lp)
{
    __half2 h = __floats2half2_rn(v0, v1);
    const float r0 = v0 - __low2float(h);
    const float r1 = v1 - __high2float(h);
    __half2 l = __floats2half2_rn(r0, r1);
    hp = *reinterpret_cast<uint32_t*>(&h);
    lp = *reinterpret_cast<uint32_t*>(&l);
}

__device__ __forceinline__ void split_store(__half* H, __half* L,
                                            size_t off, float v0, float v1)
{
    uint32_t hp, lp;
    pack_split(v0, v1, hp, lp);
    *reinterpret_cast<uint32_t*>(H + off) = hp;
    *reinterpret_cast<uint32_t*>(L + off) = lp;
}

// ---------------------------------------------------------------------------
// Fused fp32 -> fp16 hi/lo split for all six source arrays (+ counter reset)
// ---------------------------------------------------------------------------
#define A4 (ROWS * CC / 4)     // 786432 quads per activation
#define W4 (CC * CC / 4)       // 147456 quads per weight
#define CVT_TOTAL (2 * A4 + 4 * W4)

__global__ __launch_bounds__(256) void cvt_all(
    const float4* __restrict__ x, const float4* __restrict__ y,
    const float4* __restrict__ wq, const float4* __restrict__ wk,
    const float4* __restrict__ wv, const float4* __restrict__ wp)
{
    if (blockIdx.x == 0 && threadIdx.x == 0) { g_ctrP = 0; g_ctrO = 0; }

    int i = blockIdx.x * blockDim.x + threadIdx.x;
    const int stride = gridDim.x * blockDim.x;
    for (; i < CVT_TOTAL; i += stride) {
        const float4* s;
        uint2 *h, *l;
        int j;
        if (i < A4)            { s = x; h = (uint2*)g_xh; l = (uint2*)g_xl; j = i; }
        else if (i < 2 * A4)   { s = y; h = (uint2*)g_yh; l = (uint2*)g_yl; j = i - A4; }
        else {
            const int t = i - 2 * A4;
            const int w = t / W4;
            j = t - w * W4;
            if (w == 0)      { s = wq; h = (uint2*)g_wqh; l = (uint2*)g_wql; }
            else if (w == 1) { s = wk; h = (uint2*)g_wkh; l = (uint2*)g_wkl; }
            else if (w == 2) { s = wv; h = (uint2*)g_wvh; l = (uint2*)g_wvl; }
            else             { s = wp; h = (uint2*)g_wph; l = (uint2*)g_wpl; }
        }
        const float4 v = s[j];
        uint32_t h0, l0, h1, l1;
        pack_split(v.x, v.y, h0, l0);
        pack_split(v.z, v.w, h1, l1);
        h[j] = make_uint2(h0, h1);
        l[j] = make_uint2(l0, l1);
    }
}

// ---------------------------------------------------------------------------
// Persistent mma.sync NT GEMM, fp16, tile 128x64, BK=64,
// 2-stage cp.async double buffer, 256 threads (8 warps, 2m x 4n),
// warp tile 64x16, 2 CTAs/SM, dynamic tile stealing.
// OPROJ=false (proj): 3-term AhBh + AhBl + AlBh, split fp16 outputs.
// OPROJ=true  (out = O*Wp + bp): 2-term OhWph + OhWpl (O is single fp16;
//              Al never loaded -> 25% less cp.async, 33% fewer MMAs).
// ---------------------------------------------------------------------------
#define GST 72                         // padded row stride (elems), 144B
#define GTA (128 * GST)                // A tile elems (hi or lo)
#define GTB (64 * GST)                 // B tile elems (hi or lo)
#define GSTG (2 * GTA + 2 * GTB)       // elems per stage = 27648
#define GEMM_SMEM (2 * GSTG * 2)       // 110592 bytes
#define KSTEPS (CC / 64)               // 12
#define TILES_PER_MAT (32 * 12)        // 384
#define NT_PROJ (3 * TILES_PER_MAT)    // 1152
#define NT_OPROJ TILES_PER_MAT         // 384
#define GEMM_GRID 296                  // 2 per SM x 148

template <bool OPROJ>
__global__ __launch_bounds__(256, 2) void gemm_all(
    const float* __restrict__ rowbias,   // yw (proj) / nullptr
    const float* __restrict__ colbias,   // nullptr / bp
    float* __restrict__ outF)            // nullptr / out
{
    extern __shared__ char sm[];
    const uint32_t sbase = smem_u32(sm);
    __shared__ int s_tile;

    const int tid = threadIdx.x;
    const int wid = tid >> 5, lane = tid & 31;
    const int wm = wid >> 2, wn = wid & 3;          // 2 x 4 warp grid
    const int lrow = lane & 15, lcol = (lane >> 4) * 8;
    const int NT = OPROJ ? NT_OPROJ : NT_PROJ;

    for (;;) {
        if (tid == 0)
            s_tile = atomicAdd(OPROJ ? &g_ctrO : &g_ctrP, 1);
        __syncthreads();
        const int t = s_tile;
        if (t >= NT) break;

        const int z = OPROJ ? 3 : (t / TILES_PER_MAT);
        const int rem = OPROJ ? t : (t - z * TILES_PER_MAT);
        const int row0 = (rem & 31) * 128;
        const int col0 = (rem >> 5) * 64;

        const __half *Ah, *Al, *Bh, *Bl;
        __half *OH = nullptr, *OL = nullptr;
        if (OPROJ) {
            Ah = g_oh; Al = g_oh; Bh = g_wph; Bl = g_wpl;
        } else if (z == 0) {
            Ah = g_xh; Al = g_xl; Bh = g_wqh; Bl = g_wql; OH = g_qh; OL = g_ql;
        } else if (z == 1) {
            Ah = g_yh; Al = g_yl; Bh = g_wkh; Bl = g_wkl; OH = g_kh; OL = g_kl;
        } else {
            Ah = g_yh; Al = g_yl; Bh = g_wvh; Bl = g_wvl; OH = g_vh; OL = g_vl;
        }

        float acc[4][2][4];
        #pragma unroll
        for (int i = 0; i < 4; i++)
            #pragma unroll
            for (int j = 0; j < 2; j++)
                #pragma unroll
                for (int e = 0; e < 4; e++) acc[i][j][e] = 0.0f;

        auto stage_load = [&](int st, int stage) {
            const int k0 = st * 64;
            #pragma unroll
            for (int j = 0; j < 12; j++) {
                const int ch = tid + j * 256;
                if (OPROJ && ch >= 1024 && ch < 2048) continue;  // no A-lo
                const __half* src;
                uint32_t soff;
                int r, c;
                if (ch < 1024) {
                    r = ch >> 3; c = ch & 7;
                    src = Ah + (size_t)(row0 + r) * CC;
                    soff = (uint32_t)(r * GST + c * 8);
                } else if (ch < 2048) {
                    const int q = ch - 1024; r = q >> 3; c = q & 7;
                    src = Al + (size_t)(row0 + r) * CC;
                    soff = (uint32_t)(GTA + r * GST + c * 8);
                } else if (ch < 2560) {
                    const int q = ch - 2048; r = q >> 3; c = q & 7;
                    src = Bh + (size_t)(col0 + r) * CC;
                    soff = (uint32_t)(2 * GTA + r * GST + c * 8);
                } else {
                    const int q = ch - 2560; r = q >> 3; c = q & 7;
                    src = Bl + (size_t)(col0 + r) * CC;
                    soff = (uint32_t)(2 * GTA + GTB + r * GST + c * 8);
                }
                cp16(sbase + (uint32_t)(stage * GSTG) * 2 + soff * 2,
                     src + k0 + c * 8);
            }
            CP_COMMIT();
        };

        stage_load(0, 0);

        for (int st = 0; st < KSTEPS; st++) {
            const int buf = st & 1;
            if (st + 1 < KSTEPS) {
                stage_load(st + 1, buf ^ 1);
                CP_WAIT1();
            } else {
                CP_WAIT0();
            }
            __syncthreads();

            const uint32_t Ab = sbase + (uint32_t)(buf * GSTG) * 2 +
                                (uint32_t)((wm * 64 + lrow) * GST + lcol) * 2;
            const uint32_t Bb = sbase + (uint32_t)(buf * GSTG + 2 * GTA) * 2 +
                                (uint32_t)((wn * 16 + lrow) * GST + lcol) * 2;

            #pragma unroll
            for (int kk = 0; kk < 4; kk++) {
                uint32_t afh[4][4], afl[4][4];
                #pragma unroll
                for (int mt = 0; mt < 4; mt++) {
                    const uint32_t o2 = (uint32_t)(mt * 16 * GST + kk * 16) * 2;
                    ldsm4(afh[mt], Ab + o2);
                    if (!OPROJ) ldsm4(afl[mt], Ab + (uint32_t)GTA * 2 + o2);
                }
                uint32_t bh[4], bl[4];
                const uint32_t o2 = (uint32_t)(kk * 16) * 2;
                ldsm4(bh, Bb + o2);
                ldsm4(bl, Bb + (uint32_t)GTB * 2 + o2);
                #pragma unroll
                for (int mt = 0; mt < 4; mt++) {
                    mma16816(acc[mt][0], afh[mt][0], afh[mt][1], afh[mt][2], afh[mt][3], bh[0], bh[2]);
                    mma16816(acc[mt][0], afh[mt][0], afh[mt][1], afh[mt][2], afh[mt][3], bl[0], bl[2]);
                    if (!OPROJ)
                        mma16816(acc[mt][0], afl[mt][0], afl[mt][1], afl[mt][2], afl[mt][3], bh[0], bh[2]);
                    mma16816(acc[mt][1], afh[mt][0], afh[mt][1], afh[mt][2], afh[mt][3], bh[1], bh[3]);
                    mma16816(acc[mt][1], afh[mt][0], afh[mt][1], afh[mt][2], afh[mt][3], bl[1], bl[3]);
                    if (!OPROJ)
                        mma16816(acc[mt][1], afl[mt][0], afl[mt][1], afl[mt][2], afl[mt][3], bh[1], bh[3]);
                }
            }
            __syncthreads();
        }

        // Epilogue
        const float scale = (!OPROJ && z == 0) ? ATT_SCALE : 1.0f;
        #pragma unroll
        for (int mt = 0; mt < 4; mt++) {
            const int r_lo = row0 + wm * 64 + mt * 16 + (lane >> 2);
            const int r_hi = r_lo + 8;
            const float rb_lo = (!OPROJ && z == 1) ? rowbias[r_lo] : 0.0f;
            const float rb_hi = (!OPROJ && z == 1) ? rowbias[r_hi] : 0.0f;
            #pragma unroll
            for (int nt = 0; nt < 2; nt++) {
                const int c = col0 + wn * 16 + nt * 8 + 2 * (lane & 3);
                const float cb0 = OPROJ ? colbias[c] : 0.0f;
                const float cb1 = OPROJ ? colbias[c + 1] : 0.0f;
                const float v0 = acc[mt][nt][0] * scale + rb_lo + cb0;
                const float v1 = acc[mt][nt][1] * scale + rb_lo + cb1;
                const float v2 = acc[mt][nt][2] * scale + rb_hi + cb0;
                const float v3 = acc[mt][nt][3] * scale + rb_hi + cb1;
                if (OPROJ) {
                    *(float2*)(outF + (size_t)r_lo * CC + c) = make_float2(v0, v1);
                    *(float2*)(outF + (size_t)r_hi * CC + c) = make_float2(v2, v3);
                } else {
                    split_store(OH, OL, (size_t)r_lo * CC + c, v0, v1);
                    split_store(OH, OL, (size_t)r_hi * CC + c, v2, v3);
                }
            }
        }
        __syncthreads();
    }
}

// ---------------------------------------------------------------------------
// Flash attention (mma.sync, fp16 hi/lo 3-term), cp.async double-buffered K/V.
// 64 q-rows per CTA, 128 threads (4 warps x 16 rows), full 1024-key sweep,
// softmax-complete per CTA. grid (NN/64, NB*HH) = 768 CTAs, 3 CTAs/SM.
// Q staged through KV stage 0; Q pre-scaled. O written as SINGLE rn-fp16.
// ---------------------------------------------------------------------------
#define AST 72
#define KVT (64 * AST)                 // 4608 elems
#define KVSTG (4 * KVT)                // 18432 elems per stage
#define ATT_SMEM2 (2 * KVSTG * 2)      // 73728 bytes
#define NKV (MM / 64)                  // 16

__global__ __launch_bounds__(128, 3) void attn_ms()
{
    extern __shared__ char sm[];
    const uint32_t sbase = smem_u32(sm);

    const int tid = threadIdx.x;
    const int wid = tid >> 5, lane = tid & 31;
    const int lrow = lane & 15, lcol = (lane >> 4) * 8;
    const int n0 = blockIdx.x * 64;
    const int b = blockIdx.y / HH, h = blockIdx.y % HH;
    const size_t qrow0 = (size_t)(b * NN + n0);
    const size_t kvrow0 = (size_t)(b * MM);

    const int qa = tid >> 6;                    // 0..1 : qh / ql
    const __half* qsrc = qa ? g_ql : g_qh;
    const int ka = tid >> 5;                    // 0..3 : kh, kl, vh, vl
    const __half* ksrc = (ka == 0) ? g_kh : (ka == 1) ? g_kl
                       : (ka == 2) ? g_vh : g_vl;

    auto kv_load = [&](int m0i, int stage) {
        #pragma unroll
        for (int j = 0; j < 16; j++) {
            const int ch = (tid & 31) + j * 32;
            const int r = ch >> 3, c = ch & 7;
            cp16(sbase + (uint32_t)(stage * KVSTG + ka * KVT + r * AST + c * 8) * 2,
                 ksrc + (kvrow0 + m0i + r) * CC + h * DD + c * 8);
        }
        CP_COMMIT();
    };

    // ---- Q (64 rows, hi+lo) through stage 0: load, extract frags, release ----
    #pragma unroll
    for (int j = 0; j < 8; j++) {
        const int ch = (tid & 63) + j * 64;
        const int r = ch >> 3, c = ch & 7;
        cp16(sbase + (uint32_t)(qa * 64 * AST + r * AST + c * 8) * 2,
             qsrc + (qrow0 + r) * CC + h * DD + c * 8);
    }
    CP_COMMIT();
    CP_WAIT0();
    __syncthreads();

    uint32_t qfh[4][4], qfl[4][4];
    {
        const uint32_t qb = sbase + (uint32_t)((wid * 16 + lrow) * AST + lcol) * 2;
        #pragma unroll
        for (int kk = 0; kk < 4; kk++) {
            ldsm4(qfh[kk], qb + kk * 32);
            ldsm4(qfl[kk], qb + (uint32_t)(64 * AST) * 2 + kk * 32);
        }
    }
    __syncthreads();    // all warps done reading Q before stage 0 is reused

    kv_load(0, 0);

    float m0 = -1e30f, m1 = -1e30f, l0 = 0.0f, l1 = 0.0f;
    float o[8][4];
    #pragma unroll
    for (int dt = 0; dt < 8; dt++)
        #pragma unroll
        for (int e = 0; e < 4; e++) o[dt][e] = 0.0f;

    for (int st = 0; st < NKV; st++) {
        const int buf = st & 1;
        if (st + 1 < NKV) {
            kv_load((st + 1) * 64, buf ^ 1);
            CP_WAIT1();
        } else {
            CP_WAIT0();
        }
        __syncthreads();

        const uint32_t kvb = sbase + (uint32_t)(buf * KVSTG) * 2;
        const uint32_t kA = kvb + (uint32_t)(lrow * AST + lcol) * 2;
        const uint32_t vA = kvb + (uint32_t)(2 * KVT + lrow * AST + lcol) * 2;
        const uint32_t LOFS = (uint32_t)KVT * 2;

        // ---- S = Q K^T (hi/lo 3-term), Q pre-scaled ----
        float s[8][4];
        #pragma unroll
        for (int nt = 0; nt < 8; nt++)
            #pragma unroll
            for (int e = 0; e < 4; e++) s[nt][e] = 0.0f;

        #pragma unroll
        for (int kg = 0; kg < 4; kg++) {
            #pragma unroll
            for (int kk = 0; kk < 4; kk++) {
                uint32_t bh[4], bl[4];
                const uint32_t o2 = (uint32_t)(kg * 16 * AST + kk * 16) * 2;
                ldsm4(bh, kA + o2);
                ldsm4(bl, kA + LOFS + o2);
                mma16816(s[2 * kg], qfh[kk][0], qfh[kk][1], qfh[kk][2], qfh[kk][3], bh[0], bh[2]);
                mma16816(s[2 * kg], qfh[kk][0], qfh[kk][1], qfh[kk][2], qfh[kk][3], bl[0], bl[2]);
                mma16816(s[2 * kg], qfl[kk][0], qfl[kk][1], qfl[kk][2], qfl[kk][3], bh[0], bh[2]);
                mma16816(s[2 * kg + 1], qfh[kk][0], qfh[kk][1], qfh[kk][2], qfh[kk][3], bh[1], bh[3]);
                mma16816(s[2 * kg + 1], qfh[kk][0], qfh[kk][1], qfh[kk][2], qfh[kk][3], bl[1], bl[3]);
                mma16816(s[2 * kg + 1], qfl[kk][0], qfl[kk][1], qfl[kk][2], qfl[kk][3], bh[1], bh[3]);
            }
        }

        // ---- online softmax ----
        float mx0 = -1e30f, mx1 = -1e30f;
        #pragma unroll
        for (int nt = 0; nt < 8; nt++) {
            mx0 = fmaxf(mx0, fmaxf(s[nt][0], s[nt][1]));
            mx1 = fmaxf(mx1, fmaxf(s[nt][2], s[nt][3]));
        }
        mx0 = fmaxf(mx0, __shfl_xor_sync(0xFFFFFFFFu, mx0, 1));
        mx0 = fmaxf(mx0, __shfl_xor_sync(0xFFFFFFFFu, mx0, 2));
        mx1 = fmaxf(mx1, __shfl_xor_sync(0xFFFFFFFFu, mx1, 1));
        mx1 = fmaxf(mx1, __shfl_xor_sync(0xFFFFFFFFu, mx1, 2));

        const float mn0 = fmaxf(m0, mx0), mn1 = fmaxf(m1, mx1);
        const float a0 = __expf(m0 - mn0), a1 = __expf(m1 - mn1);
        m0 = mn0; m1 = mn1;

        float sum0 = 0.0f, sum1 = 0.0f;
        #pragma unroll
        for (int nt = 0; nt < 8; nt++) {
            s[nt][0] = __expf(s[nt][0] - mn0); sum0 += s[nt][0];
            s[nt][1] = __expf(s[nt][1] - mn0); sum0 += s[nt][1];
            s[nt][2] = __expf(s[nt][2] - mn1); sum1 += s[nt][2];
            s[nt][3] = __expf(s[nt][3] - mn1); sum1 += s[nt][3];
        }
        sum0 += __shfl_xor_sync(0xFFFFFFFFu, sum0, 1);
        sum0 += __shfl_xor_sync(0xFFFFFFFFu, sum0, 2);
        sum1 += __shfl_xor_sync(0xFFFFFFFFu, sum1, 1);
        sum1 += __shfl_xor_sync(0xFFFFFFFFu, sum1, 2);
        l0 = l0 * a0 + sum0;
        l1 = l1 * a1 + sum1;

        #pragma unroll
        for (int dt = 0; dt < 8; dt++) {
            o[dt][0] *= a0; o[dt][1] *= a0;
            o[dt][2] *= a1; o[dt][3] *= a1;
        }

        // ---- P -> fp16 hi/lo A-frags ----
        uint32_t ph[4][4], pl[4][4];
        #pragma unroll
        for (int kg = 0; kg < 4; kg++) {
            pack_split(s[2 * kg][0], s[2 * kg][1], ph[kg][0], pl[kg][0]);
            pack_split(s[2 * kg][2], s[2 * kg][3], ph[kg][1], pl[kg][1]);
            pack_split(s[2 * kg + 1][0], s[2 * kg + 1][1], ph[kg][2], pl[kg][2]);
            pack_split(s[2 * kg + 1][2], s[2 * kg + 1][3], ph[kg][3], pl[kg][3]);
        }

        // ---- O += P V (hi/lo 3-term) ----
        #pragma unroll
        for (int kg = 0; kg < 4; kg++) {
            #pragma unroll
            for (int dg = 0; dg < 4; dg++) {
                uint32_t vh4[4], vl4[4];
                const uint32_t o2 = (uint32_t)(kg * 16 * AST + dg * 16) * 2;
                ldsm4t(vh4, vA + o2);
                ldsm4t(vl4, vA + LOFS + o2);
                mma16816(o[2 * dg], ph[kg][0], ph[kg][1], ph[kg][2], ph[kg][3], vh4[0], vh4[1]);
                mma16816(o[2 * dg], ph[kg][0], ph[kg][1], ph[kg][2], ph[kg][3], vl4[0], vl4[1]);
                mma16816(o[2 * dg], pl[kg][0], pl[kg][1], pl[kg][2], pl[kg][3], vh4[0], vh4[1]);
                mma16816(o[2 * dg + 1], ph[kg][0], ph[kg][1], ph[kg][2], ph[kg][3], vh4[2], vh4[3]);
                mma16816(o[2 * dg + 1], ph[kg][0], ph[kg][1], ph[kg][2], ph[kg][3], vl4[2], vl4[3]);
                mma16816(o[2 * dg + 1], pl[kg][0], pl[kg][1], pl[kg][2], pl[kg][3], vh4[2], vh4[3]);
            }
        }
        __syncthreads();
    }

    // ---- normalize + store O as single rn-fp16 ----
    const float inv0 = 1.0f / l0, inv1 = 1.0f / l1;
    const size_t r_lo = qrow0 + wid * 16 + (lane >> 2);
    const size_t r_hi = r_lo + 8;
    #pragma unroll
    for (int dt = 0; dt < 8; dt++) {
        const int c = h * DD + dt * 8 + 2 * (lane & 3);
        __half2 t0 = __floats2half2_rn(o[dt][0] * inv0, o[dt][1] * inv0);
        __half2 t1 = __floats2half2_rn(o[dt][2] * inv1, o[dt][3] * inv1);
        *reinterpret_cast<uint32_t*>(g_oh + r_lo * CC + c) =
            *reinterpret_cast<uint32_t*>(&t0);
        *reinterpret_cast<uint32_t*>(g_oh + r_hi * CC + c) =
            *reinterpret_cast<uint32_t*>(&t1);
    }
}

// ---------------------------------------------------------------------------
// Launch
// ---------------------------------------------------------------------------
extern "C" void kernel_launch(void* const* d_in, const int* in_sizes, int n_in,
                              void* d_out, int out_size)
{
    const float* x  = (const float*)d_in[0];
    const float* y  = (const float*)d_in[1];
    const float* yw = (const float*)d_in[2];
    const float* Wq = (const float*)d_in[3];
    const float* Wk = (const float*)d_in[4];
    const float* Wv = (const float*)d_in[5];
    const float* Wp = (const float*)d_in[6];
    const float* bp = (const float*)d_in[7];
    float* out = (float*)d_out;

    cudaFuncSetAttribute(gemm_all<false>,
                         cudaFuncAttributeMaxDynamicSharedMemorySize, GEMM_SMEM);
    cudaFuncSetAttribute(gemm_all<true>,
                         cudaFuncAttributeMaxDynamicSharedMemorySize, GEMM_SMEM);
    cudaFuncSetAttribute(attn_ms,
                         cudaFuncAttributeMaxDynamicSharedMemorySize, ATT_SMEM2);

    // Fused fp16 hi/lo conversion of all inputs + tile-counter reset
    cvt_all<<<2112, 256>>>((const float4*)x, (const float4*)y,
                           (const float4*)Wq, (const float4*)Wk,
                           (const float4*)Wv, (const float4*)Wp);

    // Q/K/V projections: persistent, double-buffered, 3-term fp16
    gemm_all<false><<<GEMM_GRID, 256, GEMM_SMEM>>>(yw, nullptr, nullptr);

    // Attention: 64 q-rows/CTA, 3 CTAs/SM, 3-term fp16; O as single fp16
    attn_ms<<<dim3(NN / 64, NB * HH), 128, ATT_SMEM2>>>();

    // Output projection: 2-term fp16 (O single), out = O Wp^T + bp
    gemm_all<true><<<GEMM_GRID, 256, GEMM_SMEM>>>(nullptr, bp, out);
}